// round 14
// baseline (speedup 1.0000x reference)
#include <cuda_runtime.h>
#include <cuda_fp16.h>

#define NN 100000
#define EE 1600000
#define FDIM 128
#define OUTDIM 256

typedef unsigned long long ull;

// ---------------- scratch (device globals) ------------------------------------
__device__ int      g_deg[NN];
__device__ float    g_dinv[NN];
__device__ int      g_rowstart[NN + 1];
__device__ int      g_fill[NN];
__device__ int      g_srcSorted[EE];
__device__ int      g_bsum[128];
__device__ int      g_is64;
__device__ __align__(16) __half g_hh[(size_t)NN * FDIM];  // h in fp16 (gather src)
__device__ __align__(16) float  g_x[(size_t)NN * FDIM];   // layer output fp32
__device__ float    g_colsumP[FDIM * 32];
__device__ unsigned g_colmaxP[FDIM * 32];

// ---------------- packed fp32x2 helpers --------------------------------------
__device__ __forceinline__ ull ffma2(ull a, ull b, ull c) {
    ull d;
    asm("fma.rn.f32x2 %0, %1, %2, %3;" : "=l"(d) : "l"(a), "l"(b), "l"(c));
    return d;
}
__device__ __forceinline__ ull pack2(float v) {
    ull r;
    asm("mov.b64 %0, {%1, %1};" : "=l"(r) : "r"(__float_as_uint(v)));
    return r;
}

__device__ __forceinline__ int clampN(int x) {
    if (x < 0) x = 0;
    if (x >= NN) x = NN - 1;
    return x;
}

__device__ __forceinline__ int loadIdx(const int* ei32, long long pos) {
    if (g_is64) return clampN(ei32[2 * pos]);
    return clampN(ei32[pos]);
}

// ---------------- setup: init + dtype sniff (fused) ---------------------------
__global__ void __launch_bounds__(256) k_init(const int* __restrict__ ei32) {
    int i = blockIdx.x * 256 + threadIdx.x;
    if (i < NN) g_deg[i] = 1;  // self loop
    if (i < FDIM * 32) { g_colsumP[i] = 0.f; g_colmaxP[i] = 0u; }
    if (i == 0) {
        int any = 0;
        for (int j = 1; j < 1024; j += 2) any |= ei32[j];
        g_is64 = (any == 0) ? 1 : 0;
    }
}

__global__ void __launch_bounds__(256) k_count(const int* __restrict__ ei32) {
    int e = blockIdx.x * 256 + threadIdx.x;
    if (e < EE) {
        int d = loadIdx(ei32, (long long)EE + e);
        atomicAdd(&g_deg[d], 1);
    }
}

// exclusive scan of (deg-1) over N; also computes dinv (deg in hand)
__global__ void __launch_bounds__(256) k_scan1() {
    __shared__ int sh[256];
    int t = threadIdx.x;
    int base = blockIdx.x * 1024;
    int c[4]; int local = 0;
#pragma unroll
    for (int j = 0; j < 4; j++) {
        int i = base + t * 4 + j;
        int dg = (i < NN) ? g_deg[i] : 1;
        if (i < NN) g_dinv[i] = rsqrtf((float)dg);
        c[j] = (i < NN) ? (dg - 1) : 0;
        local += c[j];
    }
    sh[t] = local; __syncthreads();
#pragma unroll
    for (int off = 1; off < 256; off <<= 1) {
        int v = (t >= off) ? sh[t - off] : 0;
        __syncthreads();
        sh[t] += v;
        __syncthreads();
    }
    if (t == 255) g_bsum[blockIdx.x] = sh[255];
    int run = sh[t] - local;
#pragma unroll
    for (int j = 0; j < 4; j++) {
        int i = base + t * 4 + j;
        if (i < NN) g_rowstart[i] = run;
        run += c[j];
    }
}

__global__ void k_scan2(int nb) {
    if (threadIdx.x == 0 && blockIdx.x == 0) {
        int acc = 0;
        for (int b = 0; b < nb; b++) { int v = g_bsum[b]; g_bsum[b] = acc; acc += v; }
        g_rowstart[NN] = acc;
    }
}

__global__ void __launch_bounds__(256) k_scan3() {
    int i = blockIdx.x * 256 + threadIdx.x;
    if (i < NN) {
        int v = g_rowstart[i] + g_bsum[i >> 10];
        g_rowstart[i] = v;
        g_fill[i] = v;
    }
}

__global__ void __launch_bounds__(256) k_fill(const int* __restrict__ ei32) {
    int e = blockIdx.x * 256 + threadIdx.x;
    if (e < EE) {
        int s = loadIdx(ei32, e);
        int d = loadIdx(ei32, (long long)EE + e);
        int pos = atomicAdd(&g_fill[d], 1);
        if (pos >= 0 && pos < EE) g_srcSorted[pos] = s;
    }
}

// ---------------- dense transform: g_hh = half(X @ W) ------------------------
// R11 shape (best measured): warp = 4 rows x 128 cols; thread = 4 rows x 4 cols.
__global__ void __launch_bounds__(256) k_gemm(const float* __restrict__ Xin,
                                              int useGX,
                                              const float* __restrict__ W) {
    const float* X = useGX ? (const float*)g_x : Xin;
    int cg = threadIdx.x & 31;
    int rg = threadIdx.x >> 5;
    int r0 = blockIdx.x * 32 + rg * 4;
    int c0 = cg * 4;
    const float* x0 = X + (size_t)r0 * FDIM;

    ull a00 = 0, a01 = 0, a10 = 0, a11 = 0;
    ull a20 = 0, a21 = 0, a30 = 0, a31 = 0;

#pragma unroll 4
    for (int k = 0; k < FDIM; k += 4) {
        float4 xa = __ldg((const float4*)(x0 + k));
        float4 xb = __ldg((const float4*)(x0 + FDIM + k));
        float4 xc = __ldg((const float4*)(x0 + 2 * FDIM + k));
        float4 xd = __ldg((const float4*)(x0 + 3 * FDIM + k));
#pragma unroll
        for (int j = 0; j < 4; j++) {
            ulonglong2 w2 = __ldg((const ulonglong2*)(W + (size_t)(k + j) * FDIM + c0));
            float sa = (j == 0) ? xa.x : (j == 1) ? xa.y : (j == 2) ? xa.z : xa.w;
            float sb = (j == 0) ? xb.x : (j == 1) ? xb.y : (j == 2) ? xb.z : xb.w;
            float sc = (j == 0) ? xc.x : (j == 1) ? xc.y : (j == 2) ? xc.z : xc.w;
            float sd = (j == 0) ? xd.x : (j == 1) ? xd.y : (j == 2) ? xd.z : xd.w;
            ull pa = pack2(sa), pb = pack2(sb), pc = pack2(sc), pd = pack2(sd);
            a00 = ffma2(pa, w2.x, a00); a01 = ffma2(pa, w2.y, a01);
            a10 = ffma2(pb, w2.x, a10); a11 = ffma2(pb, w2.y, a11);
            a20 = ffma2(pc, w2.x, a20); a21 = ffma2(pc, w2.y, a21);
            a30 = ffma2(pd, w2.x, a30); a31 = ffma2(pd, w2.y, a31);
        }
    }
    // epilogue: fp32 -> fp16, 8B per row per thread
#pragma unroll
    for (int i = 0; i < 4; i++) {
        ull lo = (i == 0) ? a00 : (i == 1) ? a10 : (i == 2) ? a20 : a30;
        ull hi = (i == 0) ? a01 : (i == 1) ? a11 : (i == 2) ? a21 : a31;
        float f0 = __uint_as_float((unsigned)lo);
        float f1 = __uint_as_float((unsigned)(lo >> 32));
        float f2 = __uint_as_float((unsigned)hi);
        float f3 = __uint_as_float((unsigned)(hi >> 32));
        __half2 h0 = __floats2half2_rn(f0, f1);
        __half2 h1 = __floats2half2_rn(f2, f3);
        uint2 o = make_uint2(*(unsigned*)&h0, *(unsigned*)&h1);
        *(uint2*)(g_hh + (size_t)(r0 + i) * FDIM + c0) = o;
    }
}

// ---------------- aggregation: g_x[i] = relu(sum_e norm*h16[src] + dinv^2*h16[i] + b)
// one warp per node; lane covers 4 contiguous cols (8B fp16 load per src row).
__global__ void __launch_bounds__(256) k_agg(const float* __restrict__ bias) {
    int node = blockIdx.x * 8 + (threadIdx.x >> 5);
    int lane = threadIdx.x & 31;
    const __half* hb = g_hh;
    float di = g_dinv[node];
    float sw = di * di;

    uint2 raw = *(const uint2*)(hb + (size_t)node * FDIM + lane * 4);
    float2 f0 = __half22float2(*(__half2*)&raw.x);
    float2 f1 = __half22float2(*(__half2*)&raw.y);
    float4 acc = make_float4(f0.x * sw, f0.y * sw, f1.x * sw, f1.y * sw);

    int e = g_rowstart[node], eend = g_rowstart[node + 1];
    for (; e < eend; ++e) {
        int s = __ldg(g_srcSorted + e);
        float w = __ldg(g_dinv + s) * di;
        uint2 rv = __ldg((const uint2*)(hb + (size_t)s * FDIM + lane * 4));
        float2 g0 = __half22float2(*(__half2*)&rv.x);
        float2 g1 = __half22float2(*(__half2*)&rv.y);
        acc.x = fmaf(w, g0.x, acc.x);
        acc.y = fmaf(w, g0.y, acc.y);
        acc.z = fmaf(w, g1.x, acc.z);
        acc.w = fmaf(w, g1.y, acc.w);
    }
    float4 b = __ldg((const float4*)bias + lane);
    acc.x = fmaxf(acc.x + b.x, 0.f);
    acc.y = fmaxf(acc.y + b.y, 0.f);
    acc.z = fmaxf(acc.z + b.z, 0.f);
    acc.w = fmaxf(acc.w + b.w, 0.f);
    ((float4*)g_x)[(size_t)node * 32 + lane] = acc;
}

// ---------------- global mean + max pooling over rows of g_x -----------------
__global__ void __launch_bounds__(128) k_pool() {
    int c = threadIdx.x;
    int rbeg = blockIdx.x * 512;
    int rend = rbeg + 512; if (rend > NN) rend = NN;
    float s = 0.f, m = 0.f;  // post-relu values are >= 0
    for (int r = rbeg; r < rend; ++r) {
        float v = __ldg(&g_x[(size_t)r * FDIM + c]);
        s += v;
        m = fmaxf(m, v);
    }
    atomicAdd(&g_colsumP[c * 32], s);
    atomicMax(&g_colmaxP[c * 32], __float_as_uint(m));
}

// ---------------- final FC: out = [mean||max] @ fcW + fcb --------------------
__global__ void __launch_bounds__(256) k_fc(const float* __restrict__ fcW,
                                            const float* __restrict__ fcb,
                                            float* __restrict__ out) {
    __shared__ float pooled[2 * FDIM];
    int t = threadIdx.x;
    if (t < FDIM) pooled[t] = g_colsumP[t * 32] * (1.0f / (float)NN);
    else          pooled[t] = __uint_as_float(g_colmaxP[(t - FDIM) * 32]);
    __syncthreads();
    float a = fcb[t];
#pragma unroll 8
    for (int k = 0; k < 2 * FDIM; ++k)
        a = fmaf(pooled[k], __ldg(fcW + k * OUTDIM + t), a);
    out[t] = a;
}

// -----------------------------------------------------------------------------
extern "C" void kernel_launch(void* const* d_in, const int* in_sizes, int n_in,
                              void* d_out, int out_size) {
    const float* X = 0; const int* ei = 0;
    const float *W1 = 0, *b1 = 0, *W2 = 0, *b2 = 0, *fcW = 0, *fcb = 0;
    for (int i = 0; i < n_in; i++) {
        long long sz = in_sizes[i];
        const void* p = d_in[i];
        if      (sz == (long long)NN * FDIM)      X = (const float*)p;
        else if (sz == 2LL * EE)                  ei = (const int*)p;
        else if (sz == (long long)FDIM * FDIM)  { if (!W1) W1 = (const float*)p; else W2 = (const float*)p; }
        else if (sz == FDIM)                    { if (!b1) b1 = (const float*)p; else b2 = (const float*)p; }
        else if (sz == 2LL * FDIM * OUTDIM)       fcW = (const float*)p;
        else if (sz == OUTDIM)                    fcb = (const float*)p;
    }
    if (!X || !ei || !W1 || !b1 || !W2 || !b2 || !fcW || !fcb) {
        X   = (const float*)d_in[0];
        ei  = (const int*)d_in[1];
        W1  = (const float*)d_in[2];
        b1  = (const float*)d_in[3];
        W2  = (const float*)d_in[4];
        b2  = (const float*)d_in[5];
        fcW = (const float*)d_in[6];
        fcb = (const float*)d_in[7];
    }
    float* out = (float*)d_out;

    const int nb = (NN + 1023) / 1024;  // 98 scan blocks

    // ncu (-s 5 -c 1) profiles app launch index 3 -> k_gemm there.
    k_init<<<(NN + 255) / 256, 256>>>(ei);            // 0
    k_count<<<(EE + 255) / 256, 256>>>(ei);           // 1
    k_scan1<<<nb, 256>>>();                           // 2
    k_gemm<<<NN / 32, 256>>>(X, 0, W1);               // 3  <- profiled
    k_scan2<<<1, 32>>>(nb);                           // 4
    k_scan3<<<(NN + 255) / 256, 256>>>();             // 5
    k_fill<<<(EE + 255) / 256, 256>>>(ei);            // 6
    k_agg<<<NN / 8, 256>>>(b1);                       // 7
    k_gemm<<<NN / 32, 256>>>(X, 1, W2);               // 8
    k_agg<<<NN / 8, 256>>>(b2);                       // 9
    k_pool<<<(NN + 511) / 512, 128>>>();              // 10
    k_fc<<<1, 256>>>(fcW, fcb, out);                  // 11
}

// round 16
// speedup vs baseline: 2.0201x; 2.0201x over previous
#include <cuda_runtime.h>
#include <cuda_fp16.h>

#define NN 100000
#define EE 1600000
#define FDIM 128
#define OUTDIM 256

typedef unsigned long long ull;

// ---------------- scratch (device globals) ------------------------------------
__device__ int      g_deg[NN];
__device__ float    g_dinv[NN];
__device__ int      g_rowstart[NN + 1];
__device__ int      g_fill[NN];
__device__ int      g_srcSorted[EE];
__device__ int      g_bsum[128];
__device__ int      g_is64;
__device__ __align__(16) float g_h[(size_t)NN * FDIM];
__device__ __align__(16) float g_x[(size_t)NN * FDIM];
// W pre-packed into m16n8k16 B-fragment layout, fp16: [slot][ks][nt][lane] uint2
__device__ __align__(16) uint2 g_wfrag[2][4096];
__device__ float    g_colsumP[FDIM * 32];
__device__ unsigned g_colmaxP[FDIM * 32];

__device__ __forceinline__ int clampN(int x) {
    if (x < 0) x = 0;
    if (x >= NN) x = NN - 1;
    return x;
}

__device__ __forceinline__ int loadIdx(const int* ei32, long long pos) {
    if (g_is64) return clampN(ei32[2 * pos]);
    return clampN(ei32[pos]);
}

// ---------------- setup: init + dtype sniff (fused) ---------------------------
__global__ void __launch_bounds__(256) k_init(const int* __restrict__ ei32) {
    int i = blockIdx.x * 256 + threadIdx.x;
    if (i < NN) g_deg[i] = 1;  // self loop
    if (i < FDIM * 32) { g_colsumP[i] = 0.f; g_colmaxP[i] = 0u; }
    if (i == 0) {
        int any = 0;
        for (int j = 1; j < 1024; j += 2) any |= ei32[j];
        g_is64 = (any == 0) ? 1 : 0;
    }
}

__global__ void __launch_bounds__(256) k_count(const int* __restrict__ ei32) {
    int e = blockIdx.x * 256 + threadIdx.x;
    if (e < EE) {
        int d = loadIdx(ei32, (long long)EE + e);
        atomicAdd(&g_deg[d], 1);
    }
}

// exclusive scan of (deg-1) over N; also computes dinv (deg in hand)
__global__ void __launch_bounds__(256) k_scan1() {
    __shared__ int sh[256];
    int t = threadIdx.x;
    int base = blockIdx.x * 1024;
    int c[4]; int local = 0;
#pragma unroll
    for (int j = 0; j < 4; j++) {
        int i = base + t * 4 + j;
        int dg = (i < NN) ? g_deg[i] : 1;
        if (i < NN) g_dinv[i] = rsqrtf((float)dg);
        c[j] = (i < NN) ? (dg - 1) : 0;
        local += c[j];
    }
    sh[t] = local; __syncthreads();
#pragma unroll
    for (int off = 1; off < 256; off <<= 1) {
        int v = (t >= off) ? sh[t - off] : 0;
        __syncthreads();
        sh[t] += v;
        __syncthreads();
    }
    if (t == 255) g_bsum[blockIdx.x] = sh[255];
    int run = sh[t] - local;
#pragma unroll
    for (int j = 0; j < 4; j++) {
        int i = base + t * 4 + j;
        if (i < NN) g_rowstart[i] = run;
        run += c[j];
    }
}

__global__ void k_scan2(int nb) {
    if (threadIdx.x == 0 && blockIdx.x == 0) {
        int acc = 0;
        for (int b = 0; b < nb; b++) { int v = g_bsum[b]; g_bsum[b] = acc; acc += v; }
        g_rowstart[NN] = acc;
    }
}

__global__ void __launch_bounds__(256) k_scan3() {
    int i = blockIdx.x * 256 + threadIdx.x;
    if (i < NN) {
        int v = g_rowstart[i] + g_bsum[i >> 10];
        g_rowstart[i] = v;
        g_fill[i] = v;
    }
}

__global__ void __launch_bounds__(256) k_fill(const int* __restrict__ ei32) {
    int e = blockIdx.x * 256 + threadIdx.x;
    if (e < EE) {
        int s = loadIdx(ei32, e);
        int d = loadIdx(ei32, (long long)EE + e);
        int pos = atomicAdd(&g_fill[d], 1);
        if (pos >= 0 && pos < EE) g_srcSorted[pos] = s;
    }
}

// ---------------- W -> B-fragment pack (fp32 -> fp16, mma layout) -------------
// entry e: lane=e&31, nt=(e>>5)&15, ks=e>>9. b0,b1 = W[k0+kq+{0,1}][n];
// b2,b3 = W[k0+kq+{8,9}][n]; kq=(lane&3)*2, n=nt*8+(lane>>2), k0=ks*16.
__global__ void __launch_bounds__(256) k_prepW(const float* __restrict__ W, int slot) {
    int e = blockIdx.x * 256 + threadIdx.x;   // 4096 entries
    int lane = e & 31, nt = (e >> 5) & 15, ks = e >> 9;
    int k0 = ks * 16, kq = (lane & 3) * 2, n = nt * 8 + (lane >> 2);
    __half2 b01 = __floats2half2_rn(W[(size_t)(k0 + kq) * FDIM + n],
                                    W[(size_t)(k0 + kq + 1) * FDIM + n]);
    __half2 b23 = __floats2half2_rn(W[(size_t)(k0 + kq + 8) * FDIM + n],
                                    W[(size_t)(k0 + kq + 9) * FDIM + n]);
    g_wfrag[slot][e] = make_uint2(*(unsigned*)&b01, *(unsigned*)&b23);
}

// ---------------- tensor-core GEMM: g_h = X @ W (fp16 in, fp32 accum) --------
// 8 warps/block, 16 rows/warp = 128 rows/block. Per warp: 8 k-steps x 16 n-tiles
// of mma.m16n8k16. W fragments from smem (LDS.64, conflict-free).
__global__ void __launch_bounds__(256) k_gemmT(const float* __restrict__ Xin,
                                               int useGX, int slot) {
    __shared__ uint2 swf[4096];
    const float* X = useGX ? (const float*)g_x : Xin;
    int tid = threadIdx.x;
    for (int i = tid; i < 4096; i += 256) swf[i] = g_wfrag[slot][i];
    __syncthreads();

    int wid = tid >> 5, lane = tid & 31;
    int g = lane >> 2, kq = (lane & 3) * 2;
    int r0 = blockIdx.x * 128 + wid * 16;
    int ra = r0 + g, rb = r0 + g + 8;
    int rac = (ra < NN) ? ra : NN - 1;
    int rbc = (rb < NN) ? rb : NN - 1;
    const float* xa = X + (size_t)rac * FDIM;
    const float* xb = X + (size_t)rbc * FDIM;

    float acc[16][4];
#pragma unroll
    for (int nt = 0; nt < 16; nt++)
#pragma unroll
        for (int i = 0; i < 4; i++) acc[nt][i] = 0.f;

#pragma unroll
    for (int ks = 0; ks < 8; ks++) {
        int c = ks * 16 + kq;
        float2 pa0 = __ldg((const float2*)(xa + c));
        float2 pa1 = __ldg((const float2*)(xa + c + 8));
        float2 pb0 = __ldg((const float2*)(xb + c));
        float2 pb1 = __ldg((const float2*)(xb + c + 8));
        __half2 A0 = __floats2half2_rn(pa0.x, pa0.y);   // row g,   cols c..c+1
        __half2 A1 = __floats2half2_rn(pb0.x, pb0.y);   // row g+8, cols c..c+1
        __half2 A2 = __floats2half2_rn(pa1.x, pa1.y);   // row g,   cols c+8..9
        __half2 A3 = __floats2half2_rn(pb1.x, pb1.y);   // row g+8, cols c+8..9
        unsigned a0 = *(unsigned*)&A0, a1 = *(unsigned*)&A1;
        unsigned a2 = *(unsigned*)&A2, a3 = *(unsigned*)&A3;
        const uint2* bp = &swf[ks * 512 + lane];
#pragma unroll
        for (int nt = 0; nt < 16; nt++) {
            uint2 b = bp[nt * 32];
            asm volatile(
                "mma.sync.aligned.m16n8k16.row.col.f32.f16.f16.f32 "
                "{%0,%1,%2,%3}, {%4,%5,%6,%7}, {%8,%9}, {%0,%1,%2,%3};"
                : "+f"(acc[nt][0]), "+f"(acc[nt][1]),
                  "+f"(acc[nt][2]), "+f"(acc[nt][3])
                : "r"(a0), "r"(a1), "r"(a2), "r"(a3), "r"(b.x), "r"(b.y));
        }
    }
    // epilogue: D[g][n0..n0+1] = acc[0..1], D[g+8][n0..] = acc[2..3]
#pragma unroll
    for (int nt = 0; nt < 16; nt++) {
        int n0 = nt * 8 + kq;
        if (ra < NN)
            *(float2*)(g_h + (size_t)ra * FDIM + n0) = make_float2(acc[nt][0], acc[nt][1]);
        if (rb < NN)
            *(float2*)(g_h + (size_t)rb * FDIM + n0) = make_float2(acc[nt][2], acc[nt][3]);
    }
}

// ---------------- aggregation: g_x[i] = relu(sum_e norm*g_h[src] + dinv^2*g_h[i] + b)
// one warp per node; lane covers 4 contiguous floats (float4). No barriers.
__global__ void __launch_bounds__(256) k_agg(const float* __restrict__ bias) {
    int node = blockIdx.x * 8 + (threadIdx.x >> 5);
    int lane = threadIdx.x & 31;
    const float4* h4 = (const float4*)g_h;
    float di = g_dinv[node];
    float4 acc = __ldg(h4 + (size_t)node * 32 + lane);
    float sw = di * di;
    acc.x *= sw; acc.y *= sw; acc.z *= sw; acc.w *= sw;
    int e = g_rowstart[node], eend = g_rowstart[node + 1];
    for (; e < eend; ++e) {
        int s = __ldg(g_srcSorted + e);
        float w = __ldg(g_dinv + s) * di;
        float4 hv = __ldg(h4 + (size_t)s * 32 + lane);
        acc.x = fmaf(w, hv.x, acc.x);
        acc.y = fmaf(w, hv.y, acc.y);
        acc.z = fmaf(w, hv.z, acc.z);
        acc.w = fmaf(w, hv.w, acc.w);
    }
    float4 b = __ldg((const float4*)bias + lane);
    acc.x = fmaxf(acc.x + b.x, 0.f);
    acc.y = fmaxf(acc.y + b.y, 0.f);
    acc.z = fmaxf(acc.z + b.z, 0.f);
    acc.w = fmaxf(acc.w + b.w, 0.f);
    ((float4*)g_x)[(size_t)node * 32 + lane] = acc;
}

// ---------------- global mean + max pooling over rows of g_x -----------------
__global__ void __launch_bounds__(128) k_pool() {
    int c = threadIdx.x;
    int rbeg = blockIdx.x * 512;
    int rend = rbeg + 512; if (rend > NN) rend = NN;
    float s = 0.f, m = 0.f;  // post-relu values are >= 0
    for (int r = rbeg; r < rend; ++r) {
        float v = __ldg(&g_x[(size_t)r * FDIM + c]);
        s += v;
        m = fmaxf(m, v);
    }
    atomicAdd(&g_colsumP[c * 32], s);
    atomicMax(&g_colmaxP[c * 32], __float_as_uint(m));
}

// ---------------- final FC: out = [mean||max] @ fcW + fcb --------------------
__global__ void __launch_bounds__(256) k_fc(const float* __restrict__ fcW,
                                            const float* __restrict__ fcb,
                                            float* __restrict__ out) {
    __shared__ float pooled[2 * FDIM];
    int t = threadIdx.x;
    if (t < FDIM) pooled[t] = g_colsumP[t * 32] * (1.0f / (float)NN);
    else          pooled[t] = __uint_as_float(g_colmaxP[(t - FDIM) * 32]);
    __syncthreads();
    float a = fcb[t];
#pragma unroll 8
    for (int k = 0; k < 2 * FDIM; ++k)
        a = fmaf(pooled[k], __ldg(fcW + k * OUTDIM + t), a);
    out[t] = a;
}

// -----------------------------------------------------------------------------
extern "C" void kernel_launch(void* const* d_in, const int* in_sizes, int n_in,
                              void* d_out, int out_size) {
    const float* X = 0; const int* ei = 0;
    const float *W1 = 0, *b1 = 0, *W2 = 0, *b2 = 0, *fcW = 0, *fcb = 0;
    for (int i = 0; i < n_in; i++) {
        long long sz = in_sizes[i];
        const void* p = d_in[i];
        if      (sz == (long long)NN * FDIM)      X = (const float*)p;
        else if (sz == 2LL * EE)                  ei = (const int*)p;
        else if (sz == (long long)FDIM * FDIM)  { if (!W1) W1 = (const float*)p; else W2 = (const float*)p; }
        else if (sz == FDIM)                    { if (!b1) b1 = (const float*)p; else b2 = (const float*)p; }
        else if (sz == 2LL * FDIM * OUTDIM)       fcW = (const float*)p;
        else if (sz == OUTDIM)                    fcb = (const float*)p;
    }
    if (!X || !ei || !W1 || !b1 || !W2 || !b2 || !fcW || !fcb) {
        X   = (const float*)d_in[0];
        ei  = (const int*)d_in[1];
        W1  = (const float*)d_in[2];
        b1  = (const float*)d_in[3];
        W2  = (const float*)d_in[4];
        b2  = (const float*)d_in[5];
        fcW = (const float*)d_in[6];
        fcb = (const float*)d_in[7];
    }
    float* out = (float*)d_out;

    const int nb = (NN + 1023) / 1024;            // 98 scan blocks
    const int gemmBlocks = (NN + 127) / 128;      // 782

    // ncu (-s 5 -c 1) profiles app launch index 3 -> k_gemmT there.
    k_init<<<(NN + 255) / 256, 256>>>(ei);            // 0
    k_count<<<(EE + 255) / 256, 256>>>(ei);           // 1
    k_prepW<<<16, 256>>>(W1, 0);                      // 2
    k_gemmT<<<gemmBlocks, 256>>>(X, 0, 0);            // 3  <- profiled
    k_scan1<<<nb, 256>>>();                           // 4
    k_scan2<<<1, 32>>>(nb);                           // 5
    k_scan3<<<(NN + 255) / 256, 256>>>();             // 6
    k_fill<<<(EE + 255) / 256, 256>>>(ei);            // 7
    k_agg<<<NN / 8, 256>>>(b1);                       // 8
    k_prepW<<<16, 256>>>(W2, 1);                      // 9
    k_gemmT<<<gemmBlocks, 256>>>(X, 1, 1);            // 10
    k_agg<<<NN / 8, 256>>>(b2);                       // 11
    k_pool<<<(NN + 511) / 512, 128>>>();              // 12
    k_fc<<<1, 256>>>(fcW, fcb, out);                  // 13
}